// round 5
// baseline (speedup 1.0000x reference)
#include <cuda_runtime.h>
#include <cstdint>

// Binarized NAND-conv net. ONE WARP = ONE IMAGE; lanes parallelize spatial
// positions / output channels. 32x more warps than thread-per-image ->
// latency actually hidden.
//  L0: 1x28x28 ->16x14x14 (T=4, shfl LUT, fused into L1)
//  L1: ->16x7x7  L2: ->16x6x6  L3: ->16x3x3  L4: ->16x1x1 (T=64)
//  L5: ->10 (T=16).  bit=1 <=> +1 ; out bit = (#mismatch >= T/2).

#define NTHREADS 256
#define WARPS 8
#define IMGS_PER_BLOCK 8
#define NWORDS (IMGS_PER_BLOCK * 784 / 32)   // 196
#define FULL 0xFFFFFFFFu

__device__ __forceinline__ uint32_t nand16(uint64_t a, const uint64_t (&W)[16]) {
    uint32_t acc = 0;
#pragma unroll
    for (int oc = 0; oc < 16; oc++) {
        uint64_t x = a ^ W[oc];
        uint32_t D = __popc((uint32_t)x) + __popc((uint32_t)(x >> 32)) + 32;
        acc |= (D >> 6) << oc;   // 1 iff mismatches >= 32 (D in [32,96])
    }
    return acc;
}

__global__ void __launch_bounds__(NTHREADS, 3)
bnn_mnist_kernel(const float* __restrict__ x,
                 const float* __restrict__ w0, const float* __restrict__ w1,
                 const float* __restrict__ w2, const float* __restrict__ w3,
                 const float* __restrict__ w4, const float* __restrict__ w5,
                 float* __restrict__ out, int B)
{
    __shared__ uint32_t sbits[NWORDS + 1];
    __shared__ uint64_t sw_sh[4][16];
    __shared__ uint32_t sw0b[16];
    __shared__ uint32_t sw5s[10];
    __shared__ uint32_t sact1[WARPS][52];
    __shared__ uint32_t sact2[WARPS][40];
    __shared__ uint32_t sact3[WARPS][12];

    const int tid = threadIdx.x;
    const int lane = tid & 31;
    const int wid = tid >> 5;
    const int b0 = blockIdx.x * IMGS_PER_BLOCK;

    // ---- weight prep ----
    if (tid < 64) {
        int L = tid >> 4, oc = tid & 15;
        const float* wp = (L == 0 ? w1 : L == 1 ? w2 : L == 2 ? w3 : w4) + oc * 64;
        uint64_t v = 0;
#pragma unroll
        for (int ic = 0; ic < 16; ic++)
#pragma unroll
            for (int tap = 0; tap < 4; tap++)
                if (wp[ic * 4 + tap] > 0.0f) v |= 1ull << (tap * 16 + ic);
        sw_sh[L][oc] = v;
    } else if (tid < 80) {
        int c = tid - 64;
        uint32_t v = 0;
#pragma unroll
        for (int k = 0; k < 4; k++)
            if (w0[c * 4 + k] > 0.0f) v |= 1u << k;
        sw0b[c] = v;
    } else if (tid < 90) {
        int c = tid - 80;
        uint32_t v = 0;
#pragma unroll
        for (int ic = 0; ic < 16; ic++)
            if (w5[c * 16 + ic] > 0.0f) v |= 1u << ic;
        sw5s[c] = v;
    } else if (tid == 90) {
        sbits[NWORDS] = 0;
    }

    // ---- load + binarize + pack ----
    {
        const float* chunk = x + (size_t)b0 * 784;
        if (b0 + IMGS_PER_BLOCK <= B) {
            const float4* c4 = (const float4*)chunk;
            for (int ch = wid; ch < NWORDS / 4; ch += WARPS) {
                float4 v = c4[ch * 32 + lane];
                uint32_t nib = (uint32_t)(v.x > 0.0f) | ((uint32_t)(v.y > 0.0f) << 1)
                             | ((uint32_t)(v.z > 0.0f) << 2) | ((uint32_t)(v.w > 0.0f) << 3);
                uint32_t val = nib << (4 * (lane & 7));
                val |= __shfl_xor_sync(FULL, val, 1);
                val |= __shfl_xor_sync(FULL, val, 2);
                val |= __shfl_xor_sync(FULL, val, 4);
                if ((lane & 7) == 0) sbits[ch * 4 + (lane >> 3)] = val;
            }
        } else {
            const int nfloats = max(min(IMGS_PER_BLOCK, B - b0), 0) * 784;
            for (int w = wid; w < NWORDS; w += WARPS) {
                int f = w * 32 + lane;
                float v = (f < nfloats) ? chunk[f] : 0.0f;
                unsigned bb = __ballot_sync(FULL, v > 0.0f);
                if (lane == 0) sbits[w] = bb;
            }
        }
    }
    __syncthreads();

    // per-lane L0 LUT: lane l holds LUT[l & 15]
    uint32_t lutv = 0;
    {
        const int patch = lane & 15;
#pragma unroll
        for (int c = 0; c < 16; c++)
            lutv |= (uint32_t)(__popc((patch ^ sw0b[c]) & 0xFu) >= 2) << c;
    }

    const int img = b0 + wid;
    const int bitbase = wid * 784;

    // input rows as per-lane registers: lane l (<28) holds 28-bit row l
    uint32_t row = 0;
    if (lane < 28) {
        const int bp = bitbase + 28 * lane;
        row = __funnelshift_r(sbits[bp >> 5], sbits[(bp >> 5) + 1], bp) & 0x0FFFFFFFu;
    }

    uint64_t W[16];

    // ---- L0+L1: 49 output positions across lanes (2 shfl-safe iterations) ----
#pragma unroll
    for (int k = 0; k < 16; k++) W[k] = sw_sh[0][k];
#pragma unroll
    for (int t = 0; t < 2; t++) {
        const int p = lane + 32 * t;
        const int pc = (p < 49) ? p : 48;
        const int i = pc / 7;
        const int j = pc - 7 * i;
        const int r4 = 4 * i;
        uint32_t r0 = __shfl_sync(FULL, row, r4);
        uint32_t r1 = __shfl_sync(FULL, row, r4 + 1);
        uint32_t r2 = __shfl_sync(FULL, row, r4 + 2);
        uint32_t r3 = __shfl_sync(FULL, row, r4 + 3);
        const int s = 4 * j;
        uint32_t pA = ((r0 >> s) & 3u) | (((r1 >> s) & 3u) << 2);
        uint32_t pB = ((r0 >> (s + 2)) & 3u) | (((r1 >> (s + 2)) & 3u) << 2);
        uint32_t pC = ((r2 >> s) & 3u) | (((r3 >> s) & 3u) << 2);
        uint32_t pD = ((r2 >> (s + 2)) & 3u) | (((r3 >> (s + 2)) & 3u) << 2);
        uint32_t v00 = (uint32_t)__shfl_sync(FULL, lutv, (int)pA) & 0xFFFFu;
        uint32_t v01 = (uint32_t)__shfl_sync(FULL, lutv, (int)pB) & 0xFFFFu;
        uint32_t v10 = (uint32_t)__shfl_sync(FULL, lutv, (int)pC) & 0xFFFFu;
        uint32_t v11 = (uint32_t)__shfl_sync(FULL, lutv, (int)pD) & 0xFFFFu;
        uint64_t a64 = (uint64_t)v00 | ((uint64_t)v01 << 16)
                     | ((uint64_t)v10 << 32) | ((uint64_t)v11 << 48);
        uint32_t acc = nand16(a64, W);
        if (p < 49) sact1[wid][p] = acc;
    }
    __syncwarp();

    // ---- L2: 7x7 -> 6x6, 36 positions ----
#pragma unroll
    for (int k = 0; k < 16; k++) W[k] = sw_sh[1][k];
#pragma unroll
    for (int t = 0; t < 2; t++) {
        const int p = lane + 32 * t;
        if (p < 36) {
            const int i = p / 6;
            const int q = p + i;            // i*7 + j
            uint64_t a64 = (uint64_t)sact1[wid][q] | ((uint64_t)sact1[wid][q + 1] << 16)
                         | ((uint64_t)sact1[wid][q + 7] << 32) | ((uint64_t)sact1[wid][q + 8] << 48);
            sact2[wid][p] = nand16(a64, W);
        }
    }
    __syncwarp();

    // ---- L3: 6x6 -> 3x3, 9 positions ----
#pragma unroll
    for (int k = 0; k < 16; k++) W[k] = sw_sh[2][k];
    if (lane < 9) {
        const int i = lane / 3;
        const int j = lane - 3 * i;
        const int q = 12 * i + 2 * j;
        uint64_t a64 = (uint64_t)sact2[wid][q] | ((uint64_t)sact2[wid][q + 1] << 16)
                     | ((uint64_t)sact2[wid][q + 6] << 32) | ((uint64_t)sact2[wid][q + 7] << 48);
        sact3[wid][lane] = nand16(a64, W);
    }
    __syncwarp();

    // ---- L4: 1 position, 16 oc across lanes; assemble via ballot ----
    uint64_t a4 = (uint64_t)sact3[wid][0] | ((uint64_t)sact3[wid][1] << 16)
                | ((uint64_t)sact3[wid][3] << 32) | ((uint64_t)sact3[wid][4] << 48);
    uint64_t x4 = a4 ^ sw_sh[3][lane & 15];
    uint32_t D4 = __popc((uint32_t)x4) + __popc((uint32_t)(x4 >> 32));
    uint32_t act4 = __ballot_sync(FULL, (lane < 16) && (D4 >= 32));

    // ---- L5: 10 classes across lanes ----
    if (lane < 10 && img < B) {
        uint32_t D = __popc((act4 ^ sw5s[lane]) & 0xFFFFu);
        out[(size_t)img * 10 + lane] = (D >= 8) ? 1.0f : -1.0f;
    }
}

extern "C" void kernel_launch(void* const* d_in, const int* in_sizes, int n_in,
                              void* d_out, int out_size)
{
    const float* x  = (const float*)d_in[0];
    const float* w0 = (const float*)d_in[1];
    const float* w1 = (const float*)d_in[2];
    const float* w2 = (const float*)d_in[3];
    const float* w3 = (const float*)d_in[4];
    const float* w4 = (const float*)d_in[5];
    const float* w5 = (const float*)d_in[6];
    float* out = (float*)d_out;

    int B = in_sizes[0] / 784;
    int grid = (B + IMGS_PER_BLOCK - 1) / IMGS_PER_BLOCK;
    bnn_mnist_kernel<<<grid, NTHREADS>>>(x, w0, w1, w2, w3, w4, w5, out, B);
}

// round 6
// speedup vs baseline: 2.2204x; 2.2204x over previous
#include <cuda_runtime.h>
#include <cstdint>

// Binarized NAND-conv net. FOUR THREADS per image, split by spatial position
// (not by data needing shfl exchange): same total instruction volume as the
// thread-per-image kernel, but 4x the warps -> latency actually hidden
// without hammering the MIO pipe.
//  L0: 1x28x28 ->16x14x14 (T=4, shfl LUT, fused into L1)
//  L1: ->16x7x7  L2: ->16x6x6  L3: ->16x3x3  L4: ->16x1x1 (T=64)
//  L5: ->10 (T=16).  bit=1 <=> +1 ; out bit = (#mismatch >= T/2).

#define NTHREADS 256
#define IMGS_PER_BLOCK 64           // 4 threads per image
#define NWORDS (IMGS_PER_BLOCK * 784 / 32)   // 1568
#define S1 53   // act1 row stride (odd -> image rows hit distinct banks)
#define S2 37
#define S3 13
#define FULL 0xFFFFFFFFu

__device__ __forceinline__ uint32_t nand16(uint64_t a, const uint64_t (&W)[16]) {
    uint32_t acc = 0;
#pragma unroll
    for (int oc = 0; oc < 16; oc++) {
        uint64_t x = a ^ W[oc];
        uint32_t D = __popc((uint32_t)x) + __popc((uint32_t)(x >> 32)) + 32;
        acc |= (D >> 6) << oc;   // 1 iff mismatches >= 32 (D in [32,96])
    }
    return acc;
}

__global__ void __launch_bounds__(NTHREADS, 3)
bnn_mnist_kernel(const float* __restrict__ x,
                 const float* __restrict__ w0, const float* __restrict__ w1,
                 const float* __restrict__ w2, const float* __restrict__ w3,
                 const float* __restrict__ w4, const float* __restrict__ w5,
                 float* __restrict__ out, int B)
{
    __shared__ uint32_t sbits[NWORDS + 1];
    __shared__ uint64_t sw_sh[4][16];
    __shared__ uint32_t sw0b[16];
    __shared__ uint32_t sw5s[10];
    __shared__ uint32_t sact1[IMGS_PER_BLOCK * S1];
    __shared__ uint32_t sact2[IMGS_PER_BLOCK * S2];
    __shared__ uint32_t sact3[IMGS_PER_BLOCK * S3];

    const int tid = threadIdx.x;
    const int lane = tid & 31;
    const int b0 = blockIdx.x * IMGS_PER_BLOCK;

    // ---- weight prep ----
    if (tid < 64) {
        int L = tid >> 4, oc = tid & 15;
        const float* wp = (L == 0 ? w1 : L == 1 ? w2 : L == 2 ? w3 : w4) + oc * 64;
        uint64_t v = 0;
#pragma unroll
        for (int ic = 0; ic < 16; ic++)
#pragma unroll
            for (int tap = 0; tap < 4; tap++)
                if (wp[ic * 4 + tap] > 0.0f) v |= 1ull << (tap * 16 + ic);
        sw_sh[L][oc] = v;
    } else if (tid < 80) {
        int c = tid - 64;
        uint32_t v = 0;
#pragma unroll
        for (int k = 0; k < 4; k++)
            if (w0[c * 4 + k] > 0.0f) v |= 1u << k;
        sw0b[c] = v;
    } else if (tid < 90) {
        int c = tid - 80;
        uint32_t v = 0;
#pragma unroll
        for (int ic = 0; ic < 16; ic++)
            if (w5[c * 16 + ic] > 0.0f) v |= 1u << ic;
        sw5s[c] = v;
    } else if (tid == 90) {
        sbits[NWORDS] = 0;
    }

    // ---- load + binarize + pack ----
    {
        const int warp = tid >> 5;
        const float* chunk = x + (size_t)b0 * 784;
        if (b0 + IMGS_PER_BLOCK <= B) {
            const float4* c4 = (const float4*)chunk;
            for (int ch = warp; ch < NWORDS / 4; ch += (NTHREADS / 32)) {
                float4 v = c4[ch * 32 + lane];
                uint32_t nib = (uint32_t)(v.x > 0.0f) | ((uint32_t)(v.y > 0.0f) << 1)
                             | ((uint32_t)(v.z > 0.0f) << 2) | ((uint32_t)(v.w > 0.0f) << 3);
                uint32_t val = nib << (4 * (lane & 7));
                val |= __shfl_xor_sync(FULL, val, 1);
                val |= __shfl_xor_sync(FULL, val, 2);
                val |= __shfl_xor_sync(FULL, val, 4);
                if ((lane & 7) == 0) sbits[ch * 4 + (lane >> 3)] = val;
            }
        } else {
            const int nfloats = max(min(IMGS_PER_BLOCK, B - b0), 0) * 784;
            for (int w = warp; w < NWORDS; w += (NTHREADS / 32)) {
                int f = w * 32 + lane;
                float v = (f < nfloats) ? chunk[f] : 0.0f;
                unsigned bb = __ballot_sync(FULL, v > 0.0f);
                if (lane == 0) sbits[w] = bb;
            }
        }
    }
    __syncthreads();

    // per-lane L0 LUT: lane l holds LUT[l & 15]
    uint32_t lutv = 0;
    {
        const int patch = lane & 15;
#pragma unroll
        for (int c = 0; c < 16; c++)
            lutv |= (uint32_t)(__popc((patch ^ sw0b[c]) & 0xFu) >= 2) << c;
    }

    const int sub  = tid & 3;          // 0..3: sub-worker within image
    const int limg = tid >> 2;         // 0..63: block-local image
    const int img  = b0 + limg;
    const int bitbase = limg * 784;
    const int row1 = limg * S1;
    const int row2 = limg * S2;
    const int row3 = limg * S3;

    uint64_t W[16];

    // ---- L0+L1: rows split across subs: {0,4},{1,5},{2,6},{3} ----
#pragma unroll
    for (int k = 0; k < 16; k++) W[k] = sw_sh[0][k];
#pragma unroll
    for (int t = 0; t < 2; t++) {
        const int i = sub + 4 * t;
        const int ic = (i < 7) ? i : 6;      // clamp; keep warp converged for shfl
        const int r0 = bitbase + 112 * ic;
        int bp = r0;
        uint32_t rT0 = __funnelshift_r(sbits[bp >> 5], sbits[(bp >> 5) + 1], bp) & 0x0FFFFFFFu;
        bp = r0 + 28;
        uint32_t rB0 = __funnelshift_r(sbits[bp >> 5], sbits[(bp >> 5) + 1], bp) & 0x0FFFFFFFu;
        bp = r0 + 56;
        uint32_t rT1 = __funnelshift_r(sbits[bp >> 5], sbits[(bp >> 5) + 1], bp) & 0x0FFFFFFFu;
        bp = r0 + 84;
        uint32_t rB1 = __funnelshift_r(sbits[bp >> 5], sbits[(bp >> 5) + 1], bp) & 0x0FFFFFFFu;
#pragma unroll
        for (int j = 0; j < 7; j++) {
            const int s = 4 * j;
            uint32_t pA = ((rT0 >> s) & 3u) | (((rB0 >> s) & 3u) << 2);
            uint32_t pB = ((rT0 >> (s + 2)) & 3u) | (((rB0 >> (s + 2)) & 3u) << 2);
            uint32_t pC = ((rT1 >> s) & 3u) | (((rB1 >> s) & 3u) << 2);
            uint32_t pD = ((rT1 >> (s + 2)) & 3u) | (((rB1 >> (s + 2)) & 3u) << 2);
            uint32_t v00 = (uint32_t)__shfl_sync(FULL, lutv, (int)pA) & 0xFFFFu;
            uint32_t v01 = (uint32_t)__shfl_sync(FULL, lutv, (int)pB) & 0xFFFFu;
            uint32_t v10 = (uint32_t)__shfl_sync(FULL, lutv, (int)pC) & 0xFFFFu;
            uint32_t v11 = (uint32_t)__shfl_sync(FULL, lutv, (int)pD) & 0xFFFFu;
            uint64_t a64 = (uint64_t)v00 | ((uint64_t)v01 << 16)
                         | ((uint64_t)v10 << 32) | ((uint64_t)v11 << 48);
            uint32_t acc = nand16(a64, W);
            if (i < 7) sact1[row1 + i * 7 + j] = acc;
        }
    }
    __syncwarp();

    // ---- L2: 7x7 -> 6x6; 36 positions dealt 9 per sub (p = sub + 4k) ----
#pragma unroll
    for (int k = 0; k < 16; k++) W[k] = sw_sh[1][k];
#pragma unroll
    for (int k = 0; k < 9; k++) {
        const int p = sub + 4 * k;       // 0..35, exact cover
        const int i = p / 6;
        const int q = row1 + p + i;      // i*7 + j
        uint64_t a64 = (uint64_t)sact1[q] | ((uint64_t)sact1[q + 1] << 16)
                     | ((uint64_t)sact1[q + 7] << 32) | ((uint64_t)sact1[q + 8] << 48);
        sact2[row2 + p] = nand16(a64, W);
    }
    __syncwarp();

    // ---- L3: 6x6 -> 3x3; 9 positions: p = sub + 4k, guard p<9 ----
#pragma unroll
    for (int k = 0; k < 16; k++) W[k] = sw_sh[2][k];
#pragma unroll
    for (int k = 0; k < 3; k++) {
        const int p = sub + 4 * k;
        if (p < 9) {
            const int i = p / 3;
            const int j = p - 3 * i;
            const int q = row2 + 12 * i + 2 * j;
            uint64_t a64 = (uint64_t)sact2[q] | ((uint64_t)sact2[q + 1] << 16)
                         | ((uint64_t)sact2[q + 6] << 32) | ((uint64_t)sact2[q + 7] << 48);
            sact3[row3 + p] = nand16(a64, W);
        }
    }
    __syncwarp();

    // ---- L4: 1 position; each sub does 4 ocs, merge via shfl_xor OR ----
    uint32_t act4;
    {
        uint64_t a4 = (uint64_t)sact3[row3 + 0] | ((uint64_t)sact3[row3 + 1] << 16)
                    | ((uint64_t)sact3[row3 + 3] << 32) | ((uint64_t)sact3[row3 + 4] << 48);
        uint32_t acc = 0;
#pragma unroll
        for (int m = 0; m < 4; m++) {
            const int oc = sub * 4 + m;
            uint64_t xx = a4 ^ sw_sh[3][oc];
            uint32_t D = __popc((uint32_t)xx) + __popc((uint32_t)(xx >> 32)) + 32;
            acc |= (D >> 6) << oc;
        }
        acc |= __shfl_xor_sync(FULL, acc, 1);
        acc |= __shfl_xor_sync(FULL, acc, 2);
        act4 = acc;
    }

    // ---- L5: classes dealt per sub: {0,4,8},{1,5,9},{2,6},{3,7} ----
    if (img < B) {
        float* o = out + (size_t)img * 10;
#pragma unroll
        for (int k = 0; k < 3; k++) {
            const int oc = sub + 4 * k;
            if (oc < 10) {
                uint32_t D = __popc((act4 ^ sw5s[oc]) & 0xFFFFu);
                o[oc] = (D >= 8) ? 1.0f : -1.0f;
            }
        }
    }
}

extern "C" void kernel_launch(void* const* d_in, const int* in_sizes, int n_in,
                              void* d_out, int out_size)
{
    const float* x  = (const float*)d_in[0];
    const float* w0 = (const float*)d_in[1];
    const float* w1 = (const float*)d_in[2];
    const float* w2 = (const float*)d_in[3];
    const float* w3 = (const float*)d_in[4];
    const float* w4 = (const float*)d_in[5];
    const float* w5 = (const float*)d_in[6];
    float* out = (float*)d_out;

    int B = in_sizes[0] / 784;
    int grid = (B + IMGS_PER_BLOCK - 1) / IMGS_PER_BLOCK;
    bnn_mnist_kernel<<<grid, NTHREADS>>>(x, w0, w1, w2, w3, w4, w5, out, B);
}